// round 4
// baseline (speedup 1.0000x reference)
#include <cuda_runtime.h>
#include <cuda_fp16.h>
#include <math.h>

// ---------------------------------------------------------------------------
// Problem constants: N=131072, C=128, H=8, D=16, K=48, P=3000
// lengths in [49,143] -> bpad <= 144 -> Mpad <= 3000*144 = 432000
// ---------------------------------------------------------------------------
#define NMAX 131072
#define MPAD_MAX 432000

// Scratch (no cudaMalloc allowed). fp16 to keep module-load footprint small.
__device__ __half g_qkv_h[(size_t)NMAX * 384];   // post LN1 @ qkv_w^T + b  (~101 MB)
__device__ __half g_o_h[(size_t)MPAD_MAX * 128]; // attention output       (~111 MB)
__device__ float  g_cnt[NMAX];                   // segment counts         (0.5 MB)
// segment sums live in d_out (zeroed each call, overwritten by final kernel)

// ---------------------------------------------------------------------------
// Kernel 0: zero sums (in d_out) + cnt
// ---------------------------------------------------------------------------
__global__ void zero_kernel(float* __restrict__ sums, int n_sums4, int n_cnt) {
    int i = blockIdx.x * blockDim.x + threadIdx.x;
    int stride = gridDim.x * blockDim.x;
    float4 z = make_float4(0.f, 0.f, 0.f, 0.f);
    float4* s4 = reinterpret_cast<float4*>(sums);
    for (int k = i; k < n_sums4; k += stride) s4[k] = z;
    for (int k = i; k < n_cnt; k += stride) g_cnt[k] = 0.f;
}

// ---------------------------------------------------------------------------
// Kernel 1: LN1 + QKV GEMM.  32 rows per block, 256 threads.
// ---------------------------------------------------------------------------
__global__ __launch_bounds__(256) void ln1_qkv_kernel(
    const float* __restrict__ feat, const float* __restrict__ g1,
    const float* __restrict__ b1, const float* __restrict__ W,
    const float* __restrict__ bias, int N)
{
    extern __shared__ float sm[];
    float* h    = sm;                  // 32*128
    float* Ws   = h + 32 * 128;        // 128*129
    float* stat = Ws + 128 * 129;      // 64
    int tid  = threadIdx.x;
    int row0 = blockIdx.x * 32;

    for (int k = 0; k < 16; k++) {
        int idx = k * 256 + tid;
        h[idx] = feat[(size_t)row0 * 128 + idx];
    }
    __syncthreads();

    {
        int r = tid >> 3, j = tid & 7;
        float s = 0.f, ss = 0.f;
        #pragma unroll
        for (int it = 0; it < 16; it++) {
            float v = h[r * 128 + j * 16 + it];
            s += v; ss += v * v;
        }
        #pragma unroll
        for (int off = 4; off; off >>= 1) {
            s  += __shfl_down_sync(0xffffffffu, s, off, 8);
            ss += __shfl_down_sync(0xffffffffu, ss, off, 8);
        }
        if (j == 0) {
            float mean = s * 0.0078125f;
            float var  = ss * 0.0078125f - mean * mean;
            stat[r * 2]     = mean;
            stat[r * 2 + 1] = rsqrtf(var + 1e-5f);
        }
    }
    __syncthreads();
    {
        int col = tid & 127, half = tid >> 7;
        float g = g1[col], b = b1[col];
        #pragma unroll
        for (int rr = 0; rr < 16; rr++) {
            int r = half * 16 + rr;
            h[r * 128 + col] = (h[r * 128 + col] - stat[r * 2]) * stat[r * 2 + 1] * g + b;
        }
    }
    __syncthreads();

    int tx = tid & 31, ty = tid >> 5;
    for (int ot = 0; ot < 384; ot += 128) {
        for (int k = 0; k < 64; k++) {
            int flat = k * 256 + tid;
            int chunk = flat >> 7, i = flat & 127;
            Ws[i * 129 + chunk] = W[(size_t)(ot + chunk) * 128 + i];
        }
        __syncthreads();

        float acc[4][4];
        #pragma unroll
        for (int rr = 0; rr < 4; rr++)
            #pragma unroll
            for (int oo = 0; oo < 4; oo++)
                acc[rr][oo] = bias[ot + tx + 32 * oo];

        for (int i = 0; i < 128; i++) {
            float wv[4], hv[4];
            #pragma unroll
            for (int oo = 0; oo < 4; oo++) wv[oo] = Ws[i * 129 + tx + 32 * oo];
            #pragma unroll
            for (int rr = 0; rr < 4; rr++) hv[rr] = h[(ty * 4 + rr) * 128 + i];
            #pragma unroll
            for (int rr = 0; rr < 4; rr++)
                #pragma unroll
                for (int oo = 0; oo < 4; oo++)
                    acc[rr][oo] += hv[rr] * wv[oo];
        }

        #pragma unroll
        for (int rr = 0; rr < 4; rr++)
            #pragma unroll
            for (int oo = 0; oo < 4; oo++)
                g_qkv_h[(size_t)(row0 + ty * 4 + rr) * 384 + ot + tx + 32 * oo] =
                    __float2half(acc[rr][oo]);
        __syncthreads();
    }
}

// ---------------------------------------------------------------------------
// Kernel 2: gather + pad + RoPE + windowed attention (fp16 in, fp32 compute).
// One block per window (48 tokens). 512 threads. Warp = single head.
// ---------------------------------------------------------------------------
__global__ __launch_bounds__(512) void attn_kernel(
    const int* __restrict__ pinv, const int* __restrict__ pad,
    const float* __restrict__ cosb, const float* __restrict__ sinb)
{
    extern __shared__ float sm[];
    float* qs = sm;                 // 48*128
    float* ks = sm + 48 * 128;
    float* vs = sm + 2 * 48 * 128;
    int tid = threadIdx.x;
    int w = blockIdx.x;

    if (tid < 384) {
        int r = tid >> 3, seg = tid & 7;
        int pj  = pad[w * 48 + r];
        int src = pinv[pj];
        const uint4* rowp = reinterpret_cast<const uint4*>(g_qkv_h + (size_t)src * 384 + seg * 48);
        #pragma unroll
        for (int blk = 0; blk < 3; blk++) {
            int off = seg * 48 + blk * 16;
            int t = off >> 7, c = off & 127;
            uint4 u0 = rowp[blk * 2 + 0];   // 8 halves
            uint4 u1 = rowp[blk * 2 + 1];   // 8 halves
            const __half2* hp0 = reinterpret_cast<const __half2*>(&u0);
            const __half2* hp1 = reinterpret_cast<const __half2*>(&u1);
            float vals[16];
            #pragma unroll
            for (int i = 0; i < 4; i++) {
                float2 f = __half22float2(hp0[i]);
                vals[2 * i] = f.x; vals[2 * i + 1] = f.y;
            }
            #pragma unroll
            for (int i = 0; i < 4; i++) {
                float2 f = __half22float2(hp1[i]);
                vals[8 + 2 * i] = f.x; vals[8 + 2 * i + 1] = f.y;
            }
            if (t < 2) {   // rope q and k (chunk == one head, D=16)
                #pragma unroll
                for (int d = 0; d < 8; d++) {
                    float cv = cosb[(size_t)pj * 16 + d];
                    float sv = sinb[(size_t)pj * 16 + d];
                    float x1 = vals[d], x2 = vals[d + 8];
                    vals[d]     = x1 * cv - x2 * sv;
                    vals[d + 8] = x2 * cv + x1 * sv;
                }
            }
            float* dst = (t == 0) ? qs : ((t == 1) ? ks : vs);
            float4* d4 = reinterpret_cast<float4*>(dst + r * 128 + c);
            d4[0] = make_float4(vals[0], vals[1], vals[2], vals[3]);
            d4[1] = make_float4(vals[4], vals[5], vals[6], vals[7]);
            d4[2] = make_float4(vals[8], vals[9], vals[10], vals[11]);
            d4[3] = make_float4(vals[12], vals[13], vals[14], vals[15]);
        }
    }
    __syncthreads();

    int h = tid >> 6;        // head
    int r = tid & 63;        // query row
    if (r < 48) {
        const float4* qp = reinterpret_cast<const float4*>(qs + r * 128 + h * 16);
        float4 q0 = qp[0], q1 = qp[1], q2 = qp[2], q3 = qp[3];

        float sc[48];
        float mx = -1e30f;
        #pragma unroll
        for (int kk = 0; kk < 48; kk++) {
            const float4* kp = reinterpret_cast<const float4*>(ks + kk * 128 + h * 16);
            float4 k0 = kp[0], k1 = kp[1], k2 = kp[2], k3 = kp[3];
            float a = q0.x * k0.x + q0.y * k0.y + q0.z * k0.z + q0.w * k0.w
                    + q1.x * k1.x + q1.y * k1.y + q1.z * k1.z + q1.w * k1.w
                    + q2.x * k2.x + q2.y * k2.y + q2.z * k2.z + q2.w * k2.w
                    + q3.x * k3.x + q3.y * k3.y + q3.z * k3.z + q3.w * k3.w;
            a *= 0.25f;
            sc[kk] = a;
            mx = fmaxf(mx, a);
        }
        float sum = 0.f;
        #pragma unroll
        for (int kk = 0; kk < 48; kk++) {
            float e = __expf(sc[kk] - mx);
            sc[kk] = e;
            sum += e;
        }
        float inv = 1.f / sum;
        float acc[16];
        #pragma unroll
        for (int d = 0; d < 16; d++) acc[d] = 0.f;
        #pragma unroll
        for (int kk = 0; kk < 48; kk++) {
            float p = sc[kk] * inv;
            const float4* vp = reinterpret_cast<const float4*>(vs + kk * 128 + h * 16);
            float4 v0 = vp[0], v1 = vp[1], v2 = vp[2], v3 = vp[3];
            acc[0] += p * v0.x;  acc[1] += p * v0.y;  acc[2] += p * v0.z;  acc[3] += p * v0.w;
            acc[4] += p * v1.x;  acc[5] += p * v1.y;  acc[6] += p * v1.z;  acc[7] += p * v1.w;
            acc[8] += p * v2.x;  acc[9] += p * v2.y;  acc[10] += p * v2.z; acc[11] += p * v2.w;
            acc[12] += p * v3.x; acc[13] += p * v3.y; acc[14] += p * v3.z; acc[15] += p * v3.w;
        }
        uint4 ou[2];
        __half2* oh = reinterpret_cast<__half2*>(ou);
        #pragma unroll
        for (int i = 0; i < 8; i++)
            oh[i] = __floats2half2_rn(acc[2 * i], acc[2 * i + 1]);
        uint4* op = reinterpret_cast<uint4*>(g_o_h + (size_t)(w * 48 + r) * 128 + h * 16);
        op[0] = ou[0];
        op[1] = ou[1];
    }
}

// ---------------------------------------------------------------------------
// Kernel 3: unpad gather + proj GEMM + segment scatter-add into sums (d_out).
// ---------------------------------------------------------------------------
__global__ __launch_bounds__(256) void proj_kernel(
    const float* __restrict__ W, const float* __restrict__ bias,
    const int* __restrict__ unpad, const int* __restrict__ pinv,
    float* __restrict__ sums, int M)
{
    extern __shared__ float sm[];
    float* rows = sm;                   // 32*128
    float* Ws   = rows + 32 * 128;      // 128*129
    int*   us   = reinterpret_cast<int*>(Ws + 128 * 129);  // 32
    int*   pis  = us + 32;                                  // 32
    int tid = threadIdx.x;
    int m0 = blockIdx.x * 32;

    if (tid < 32) {
        int m = m0 + tid;
        us[tid]  = (m < M) ? unpad[m] : 0;
        pis[tid] = (m < M) ? pinv[m] : -1;
    }
    __syncthreads();

    for (int k = 0; k < 2; k++) {
        int flat = k * 256 + tid;       // 0..511 : 32 rows x 16 groups of 8 halves
        int r = flat >> 4, grp = flat & 15;
        uint4 u;
        if (pis[r] >= 0) {
            u = reinterpret_cast<const uint4*>(g_o_h + (size_t)us[r] * 128)[grp];
        } else {
            u = make_uint4(0, 0, 0, 0);
        }
        const __half2* hp = reinterpret_cast<const __half2*>(&u);
        #pragma unroll
        for (int i = 0; i < 4; i++) {
            float2 f = __half22float2(hp[i]);
            rows[r * 128 + grp * 8 + 2 * i]     = f.x;
            rows[r * 128 + grp * 8 + 2 * i + 1] = f.y;
        }
    }
    for (int k = 0; k < 64; k++) {
        int flat = k * 256 + tid;
        int chunk = flat >> 7, i = flat & 127;
        Ws[i * 129 + chunk] = W[(size_t)chunk * 128 + i];
    }
    __syncthreads();

    int tx = tid & 31, ty = tid >> 5;
    float acc[4][4];
    #pragma unroll
    for (int rr = 0; rr < 4; rr++)
        #pragma unroll
        for (int oo = 0; oo < 4; oo++)
            acc[rr][oo] = bias[tx + 32 * oo];
    for (int i = 0; i < 128; i++) {
        float wv[4], hv[4];
        #pragma unroll
        for (int oo = 0; oo < 4; oo++) wv[oo] = Ws[i * 129 + tx + 32 * oo];
        #pragma unroll
        for (int rr = 0; rr < 4; rr++) hv[rr] = rows[(ty * 4 + rr) * 128 + i];
        #pragma unroll
        for (int rr = 0; rr < 4; rr++)
            #pragma unroll
            for (int oo = 0; oo < 4; oo++)
                acc[rr][oo] += hv[rr] * wv[oo];
    }
    #pragma unroll
    for (int rr = 0; rr < 4; rr++) {
        int pi = pis[ty * 4 + rr];
        if (pi >= 0) {
            #pragma unroll
            for (int oo = 0; oo < 4; oo++)
                atomicAdd(&sums[(size_t)pi * 128 + tx + 32 * oo], acc[rr][oo]);
        }
    }
    if (tid < 32 && pis[tid] >= 0) atomicAdd(&g_cnt[pis[tid]], 1.0f);
}

// ---------------------------------------------------------------------------
// Kernel 4: x = feat + sums/max(cnt,1); LN2; FC1+GELU; FC2; out = x + mlp.
// sums is read from d_out, final result overwrites d_out (read-before-write
// per element within each block's own rows).
// ---------------------------------------------------------------------------
__global__ __launch_bounds__(256) void mlp_kernel(
    const float* __restrict__ feat,
    const float* __restrict__ g2, const float* __restrict__ b2,
    const float* __restrict__ fc1_w, const float* __restrict__ fc1_b,
    const float* __restrict__ fc2_w, const float* __restrict__ fc2_b,
    float* __restrict__ out, int N)
{
    extern __shared__ float sm[];
    float* x    = sm;                   // 32*128
    float* h2   = x + 32 * 128;         // 32*128
    float* u    = h2 + 32 * 128;        // 32*512
    float* Ws   = u + 32 * 512;         // 128*129
    float* stat = Ws + 128 * 129;       // 64
    int tid = threadIdx.x;
    int row0 = blockIdx.x * 32;

    for (int k = 0; k < 16; k++) {
        int idx = k * 256 + tid;
        int r = idx >> 7, c = idx & 127;
        int row = row0 + r;
        float cv = g_cnt[row];
        x[idx] = feat[(size_t)row * 128 + c] + out[(size_t)row * 128 + c] / fmaxf(cv, 1.0f);
    }
    __syncthreads();

    {
        int r = tid >> 3, j = tid & 7;
        float s = 0.f, ss = 0.f;
        #pragma unroll
        for (int it = 0; it < 16; it++) {
            float v = x[r * 128 + j * 16 + it];
            s += v; ss += v * v;
        }
        #pragma unroll
        for (int off = 4; off; off >>= 1) {
            s  += __shfl_down_sync(0xffffffffu, s, off, 8);
            ss += __shfl_down_sync(0xffffffffu, ss, off, 8);
        }
        if (j == 0) {
            float mean = s * 0.0078125f;
            float var  = ss * 0.0078125f - mean * mean;
            stat[r * 2]     = mean;
            stat[r * 2 + 1] = rsqrtf(var + 1e-5f);
        }
    }
    __syncthreads();
    {
        int col = tid & 127, half = tid >> 7;
        float g = g2[col], b = b2[col];
        #pragma unroll
        for (int rr = 0; rr < 16; rr++) {
            int r = half * 16 + rr;
            h2[r * 128 + col] = (x[r * 128 + col] - stat[r * 2]) * stat[r * 2 + 1] * g + b;
        }
    }
    __syncthreads();

    int tx = tid & 31, ty = tid >> 5;

    for (int ot = 0; ot < 512; ot += 128) {
        for (int k = 0; k < 64; k++) {
            int flat = k * 256 + tid;
            int chunk = flat >> 7, i = flat & 127;
            Ws[i * 129 + chunk] = fc1_w[(size_t)(ot + chunk) * 128 + i];
        }
        __syncthreads();
        float acc[4][4];
        #pragma unroll
        for (int rr = 0; rr < 4; rr++)
            #pragma unroll
            for (int oo = 0; oo < 4; oo++)
                acc[rr][oo] = fc1_b[ot + tx + 32 * oo];
        for (int i = 0; i < 128; i++) {
            float wv[4], hv[4];
            #pragma unroll
            for (int oo = 0; oo < 4; oo++) wv[oo] = Ws[i * 129 + tx + 32 * oo];
            #pragma unroll
            for (int rr = 0; rr < 4; rr++) hv[rr] = h2[(ty * 4 + rr) * 128 + i];
            #pragma unroll
            for (int rr = 0; rr < 4; rr++)
                #pragma unroll
                for (int oo = 0; oo < 4; oo++)
                    acc[rr][oo] += hv[rr] * wv[oo];
        }
        #pragma unroll
        for (int rr = 0; rr < 4; rr++)
            #pragma unroll
            for (int oo = 0; oo < 4; oo++) {
                float v = acc[rr][oo];
                float gelu = 0.5f * v * (1.0f + erff(v * 0.70710678118f));
                u[(ty * 4 + rr) * 512 + ot + tx + 32 * oo] = gelu;
            }
        __syncthreads();
    }

    float acc2[4][4];
    #pragma unroll
    for (int rr = 0; rr < 4; rr++)
        #pragma unroll
        for (int oo = 0; oo < 4; oo++)
            acc2[rr][oo] = fc2_b[tx + 32 * oo];
    for (int kt = 0; kt < 512; kt += 128) {
        for (int k = 0; k < 64; k++) {
            int flat = k * 256 + tid;
            int c = flat >> 7, kk = flat & 127;
            Ws[kk * 129 + c] = fc2_w[(size_t)c * 512 + kt + kk];
        }
        __syncthreads();
        for (int kk = 0; kk < 128; kk++) {
            float wv[4], uv[4];
            #pragma unroll
            for (int oo = 0; oo < 4; oo++) wv[oo] = Ws[kk * 129 + tx + 32 * oo];
            #pragma unroll
            for (int rr = 0; rr < 4; rr++) uv[rr] = u[(ty * 4 + rr) * 512 + kt + kk];
            #pragma unroll
            for (int rr = 0; rr < 4; rr++)
                #pragma unroll
                for (int oo = 0; oo < 4; oo++)
                    acc2[rr][oo] += uv[rr] * wv[oo];
        }
        __syncthreads();
    }

    #pragma unroll
    for (int rr = 0; rr < 4; rr++)
        #pragma unroll
        for (int oo = 0; oo < 4; oo++) {
            int r = ty * 4 + rr, c = tx + 32 * oo;
            out[(size_t)(row0 + r) * 128 + c] = x[r * 128 + c] + acc2[rr][oo];
        }
}

// ---------------------------------------------------------------------------
// Host
// ---------------------------------------------------------------------------
extern "C" void kernel_launch(void* const* d_in, const int* in_sizes, int n_in,
                              void* d_out, int out_size)
{
    const float* feat   = (const float*)d_in[0];
    const float* cosb   = (const float*)d_in[1];
    const float* sinb   = (const float*)d_in[2];
    const float* g1     = (const float*)d_in[3];
    const float* b1     = (const float*)d_in[4];
    const float* qkv_w  = (const float*)d_in[5];
    const float* qkv_b  = (const float*)d_in[6];
    const float* proj_w = (const float*)d_in[7];
    const float* proj_b = (const float*)d_in[8];
    const float* g2     = (const float*)d_in[9];
    const float* b2     = (const float*)d_in[10];
    const float* fc1_w  = (const float*)d_in[11];
    const float* fc1_b  = (const float*)d_in[12];
    const float* fc2_w  = (const float*)d_in[13];
    const float* fc2_b  = (const float*)d_in[14];
    const int*   pinv   = (const int*)d_in[15];
    const int*   pad    = (const int*)d_in[16];
    const int*   unpad  = (const int*)d_in[17];

    int N    = in_sizes[0] / 128;
    int M    = in_sizes[15];
    int Mpad = in_sizes[16];
    int Wn   = Mpad / 48;

    float* out_f = (float*)d_out;

    const int LN1_SMEM  = (32 * 128 + 128 * 129 + 64) * 4;
    const int ATTN_SMEM = 3 * 48 * 128 * 4;
    const int PROJ_SMEM = (32 * 128 + 128 * 129) * 4 + 64 * 4;
    const int MLP_SMEM  = (32 * 128 * 2 + 32 * 512 + 128 * 129 + 64) * 4;

    cudaFuncSetAttribute(ln1_qkv_kernel, cudaFuncAttributeMaxDynamicSharedMemorySize, LN1_SMEM);
    cudaFuncSetAttribute(attn_kernel,    cudaFuncAttributeMaxDynamicSharedMemorySize, ATTN_SMEM);
    cudaFuncSetAttribute(proj_kernel,    cudaFuncAttributeMaxDynamicSharedMemorySize, PROJ_SMEM);
    cudaFuncSetAttribute(mlp_kernel,     cudaFuncAttributeMaxDynamicSharedMemorySize, MLP_SMEM);

    zero_kernel<<<2048, 256>>>(out_f, N * 128 / 4, N);
    ln1_qkv_kernel<<<N / 32, 256, LN1_SMEM>>>(feat, g1, b1, qkv_w, qkv_b, N);
    attn_kernel<<<Wn, 512, ATTN_SMEM>>>(pinv, pad, cosb, sinb);
    proj_kernel<<<(M + 31) / 32, 256, PROJ_SMEM>>>(proj_w, proj_b, unpad, pinv, out_f, M);
    mlp_kernel<<<N / 32, 256, MLP_SMEM>>>(feat, g2, b2, fc1_w, fc1_b, fc2_w, fc2_b,
                                          out_f, N);
}

// round 5
// speedup vs baseline: 1.2935x; 1.2935x over previous
#include <cuda_runtime.h>
#include <cuda_fp16.h>
#include <mma.h>
#include <math.h>

using namespace nvcuda;

// ---------------------------------------------------------------------------
// Problem constants: N=131072, C=128, H=8, D=16, K=48, P=3000
// Mpad <= 3000*144 = 432000
// ---------------------------------------------------------------------------
#define NMAX 131072
#define MPAD_MAX 432000

__device__ __half g_qkv_h[(size_t)NMAX * 384];   // ~101 MB
__device__ __half g_o_h[(size_t)MPAD_MAX * 128]; // ~111 MB
__device__ float  g_cnt[NMAX];
// segment sums live in d_out

// ---------------------------------------------------------------------------
// Kernel 0: zero sums (in d_out) + cnt
// ---------------------------------------------------------------------------
__global__ void zero_kernel(float* __restrict__ sums, int n_sums4, int n_cnt) {
    int i = blockIdx.x * blockDim.x + threadIdx.x;
    int stride = gridDim.x * blockDim.x;
    float4 z = make_float4(0.f, 0.f, 0.f, 0.f);
    float4* s4 = reinterpret_cast<float4*>(sums);
    for (int k = i; k < n_sums4; k += stride) s4[k] = z;
    for (int k = i; k < n_cnt; k += stride) g_cnt[k] = 0.f;
}

// ---------------------------------------------------------------------------
// Kernel 1: LN1 + QKV GEMM (tensor cores). 64 rows/block, 256 threads.
// smem: xf f32[64*128] (reused as C f32), stat[128], A half[64*128],
//       B half[128*128]
// ---------------------------------------------------------------------------
__global__ __launch_bounds__(256) void ln1_qkv_tc(
    const float* __restrict__ feat, const float* __restrict__ g1,
    const float* __restrict__ b1, const float* __restrict__ W,
    const float* __restrict__ bias)
{
    extern __shared__ char smraw[];
    float*  xf   = reinterpret_cast<float*>(smraw);            // 32768 B (also C)
    float*  stat = reinterpret_cast<float*>(smraw + 32768);    // 512 B
    __half* A    = reinterpret_cast<__half*>(smraw + 33280);   // 16384 B
    __half* B    = reinterpret_cast<__half*>(smraw + 49664);   // 32768 B
    int tid  = threadIdx.x;
    int row0 = blockIdx.x * 64;

    // load 64 rows of feat
    #pragma unroll
    for (int it = 0; it < 8; it++) {
        int idx4 = it * 256 + tid;                 // 2048 float4
        reinterpret_cast<float4*>(xf)[idx4] =
            reinterpret_cast<const float4*>(feat + (size_t)row0 * 128)[idx4];
    }
    __syncthreads();

    // LN stats: 4 threads per row
    {
        int r = tid >> 2, j = tid & 3;
        float s = 0.f, ss = 0.f;
        #pragma unroll
        for (int it = 0; it < 32; it++) {
            float v = xf[r * 128 + j * 32 + it];
            s += v; ss += v * v;
        }
        s  += __shfl_down_sync(0xffffffffu, s, 2, 4);
        ss += __shfl_down_sync(0xffffffffu, ss, 2, 4);
        s  += __shfl_down_sync(0xffffffffu, s, 1, 4);
        ss += __shfl_down_sync(0xffffffffu, ss, 1, 4);
        if (j == 0) {
            float mean = s * 0.0078125f;
            float var  = ss * 0.0078125f - mean * mean;
            stat[r * 2]     = mean;
            stat[r * 2 + 1] = rsqrtf(var + 1e-5f);
        }
    }
    __syncthreads();

    // normalize -> A (half)
    #pragma unroll
    for (int it = 0; it < 32; it++) {
        int idx = it * 256 + tid;
        int r = idx >> 7, c = idx & 127;
        float v = (xf[idx] - stat[r * 2]) * stat[r * 2 + 1] * g1[c] + b1[c];
        A[idx] = __float2half(v);
    }
    __syncthreads();

    int w = tid >> 5;   // warp 0..7 -> output col tile
    for (int ot = 0; ot < 384; ot += 128) {
        // convert W tile -> B half, layout preserved (col_major fragment)
        #pragma unroll
        for (int it = 0; it < 64; it++) {
            int flat = it * 256 + tid;             // 16384
            B[flat] = __float2half(W[(size_t)ot * 128 + flat]);
        }
        __syncthreads();

        wmma::fragment<wmma::accumulator, 16, 16, 16, float> fc[4];
        #pragma unroll
        for (int rt = 0; rt < 4; rt++) wmma::fill_fragment(fc[rt], 0.f);
        #pragma unroll
        for (int kk = 0; kk < 8; kk++) {
            wmma::fragment<wmma::matrix_b, 16, 16, 16, __half, wmma::col_major> fb;
            wmma::load_matrix_sync(fb, B + w * 16 * 128 + kk * 16, 128);
            #pragma unroll
            for (int rt = 0; rt < 4; rt++) {
                wmma::fragment<wmma::matrix_a, 16, 16, 16, __half, wmma::row_major> fa;
                wmma::load_matrix_sync(fa, A + rt * 16 * 128 + kk * 16, 128);
                wmma::mma_sync(fc[rt], fa, fb, fc[rt]);
            }
        }
        __syncthreads();   // xf (=C) free
        #pragma unroll
        for (int rt = 0; rt < 4; rt++)
            wmma::store_matrix_sync(xf + rt * 16 * 128 + w * 16, fc[rt], 128,
                                    wmma::mem_row_major);
        __syncthreads();

        #pragma unroll
        for (int it = 0; it < 32; it++) {
            int idx = it * 256 + tid;
            int r = idx >> 7, c = idx & 127;
            g_qkv_h[(size_t)(row0 + r) * 384 + ot + c] =
                __float2half(xf[idx] + bias[ot + c]);
        }
        __syncthreads();
    }
}

// ---------------------------------------------------------------------------
// Kernel 2: gather + pad + RoPE + windowed attention (unchanged).
// ---------------------------------------------------------------------------
__global__ __launch_bounds__(512) void attn_kernel(
    const int* __restrict__ pinv, const int* __restrict__ pad,
    const float* __restrict__ cosb, const float* __restrict__ sinb)
{
    extern __shared__ float sm[];
    float* qs = sm;
    float* ks = sm + 48 * 128;
    float* vs = sm + 2 * 48 * 128;
    int tid = threadIdx.x;
    int w = blockIdx.x;

    if (tid < 384) {
        int r = tid >> 3, seg = tid & 7;
        int pj  = pad[w * 48 + r];
        int src = pinv[pj];
        const uint4* rowp = reinterpret_cast<const uint4*>(g_qkv_h + (size_t)src * 384 + seg * 48);
        #pragma unroll
        for (int blk = 0; blk < 3; blk++) {
            int off = seg * 48 + blk * 16;
            int t = off >> 7, c = off & 127;
            uint4 u0 = rowp[blk * 2 + 0];
            uint4 u1 = rowp[blk * 2 + 1];
            const __half2* hp0 = reinterpret_cast<const __half2*>(&u0);
            const __half2* hp1 = reinterpret_cast<const __half2*>(&u1);
            float vals[16];
            #pragma unroll
            for (int i = 0; i < 4; i++) {
                float2 f = __half22float2(hp0[i]);
                vals[2 * i] = f.x; vals[2 * i + 1] = f.y;
            }
            #pragma unroll
            for (int i = 0; i < 4; i++) {
                float2 f = __half22float2(hp1[i]);
                vals[8 + 2 * i] = f.x; vals[8 + 2 * i + 1] = f.y;
            }
            if (t < 2) {
                #pragma unroll
                for (int d = 0; d < 8; d++) {
                    float cv = cosb[(size_t)pj * 16 + d];
                    float sv = sinb[(size_t)pj * 16 + d];
                    float x1 = vals[d], x2 = vals[d + 8];
                    vals[d]     = x1 * cv - x2 * sv;
                    vals[d + 8] = x2 * cv + x1 * sv;
                }
            }
            float* dst = (t == 0) ? qs : ((t == 1) ? ks : vs);
            float4* d4 = reinterpret_cast<float4*>(dst + r * 128 + c);
            d4[0] = make_float4(vals[0], vals[1], vals[2], vals[3]);
            d4[1] = make_float4(vals[4], vals[5], vals[6], vals[7]);
            d4[2] = make_float4(vals[8], vals[9], vals[10], vals[11]);
            d4[3] = make_float4(vals[12], vals[13], vals[14], vals[15]);
        }
    }
    __syncthreads();

    int h = tid >> 6;
    int r = tid & 63;
    if (r < 48) {
        const float4* qp = reinterpret_cast<const float4*>(qs + r * 128 + h * 16);
        float4 q0 = qp[0], q1 = qp[1], q2 = qp[2], q3 = qp[3];

        float sc[48];
        float mx = -1e30f;
        #pragma unroll
        for (int kk = 0; kk < 48; kk++) {
            const float4* kp = reinterpret_cast<const float4*>(ks + kk * 128 + h * 16);
            float4 k0 = kp[0], k1 = kp[1], k2 = kp[2], k3 = kp[3];
            float a = q0.x * k0.x + q0.y * k0.y + q0.z * k0.z + q0.w * k0.w
                    + q1.x * k1.x + q1.y * k1.y + q1.z * k1.z + q1.w * k1.w
                    + q2.x * k2.x + q2.y * k2.y + q2.z * k2.z + q2.w * k2.w
                    + q3.x * k3.x + q3.y * k3.y + q3.z * k3.z + q3.w * k3.w;
            a *= 0.25f;
            sc[kk] = a;
            mx = fmaxf(mx, a);
        }
        float sum = 0.f;
        #pragma unroll
        for (int kk = 0; kk < 48; kk++) {
            float e = __expf(sc[kk] - mx);
            sc[kk] = e;
            sum += e;
        }
        float inv = 1.f / sum;
        float acc[16];
        #pragma unroll
        for (int d = 0; d < 16; d++) acc[d] = 0.f;
        #pragma unroll
        for (int kk = 0; kk < 48; kk++) {
            float p = sc[kk] * inv;
            const float4* vp = reinterpret_cast<const float4*>(vs + kk * 128 + h * 16);
            float4 v0 = vp[0], v1 = vp[1], v2 = vp[2], v3 = vp[3];
            acc[0] += p * v0.x;  acc[1] += p * v0.y;  acc[2] += p * v0.z;  acc[3] += p * v0.w;
            acc[4] += p * v1.x;  acc[5] += p * v1.y;  acc[6] += p * v1.z;  acc[7] += p * v1.w;
            acc[8] += p * v2.x;  acc[9] += p * v2.y;  acc[10] += p * v2.z; acc[11] += p * v2.w;
            acc[12] += p * v3.x; acc[13] += p * v3.y; acc[14] += p * v3.z; acc[15] += p * v3.w;
        }
        uint4 ou[2];
        __half2* oh = reinterpret_cast<__half2*>(ou);
        #pragma unroll
        for (int i = 0; i < 8; i++)
            oh[i] = __floats2half2_rn(acc[2 * i], acc[2 * i + 1]);
        uint4* op = reinterpret_cast<uint4*>(g_o_h + (size_t)(w * 48 + r) * 128 + h * 16);
        op[0] = ou[0];
        op[1] = ou[1];
    }
}

// ---------------------------------------------------------------------------
// Kernel 3: unpad gather + proj GEMM (tensor cores) + segment scatter-add.
// 64 rows/block, 256 threads.
// smem: A half[64*128], BC union (B half[128*128] / C f32[64*128]), idx
// ---------------------------------------------------------------------------
__global__ __launch_bounds__(256) void proj_tc(
    const float* __restrict__ W, const float* __restrict__ bias,
    const int* __restrict__ unpad, const int* __restrict__ pinv,
    float* __restrict__ sums, int M)
{
    extern __shared__ char smraw[];
    __half* A  = reinterpret_cast<__half*>(smraw);            // 16384 B
    __half* B  = reinterpret_cast<__half*>(smraw + 16384);    // 32768 B (union C)
    float*  Cf = reinterpret_cast<float*>(smraw + 16384);
    int*    us  = reinterpret_cast<int*>(smraw + 49152);      // 64
    int*    pis = us + 64;                                     // 64
    int tid = threadIdx.x;
    int m0 = blockIdx.x * 64;

    if (tid < 64) {
        int m = m0 + tid;
        us[tid]  = (m < M) ? unpad[m] : 0;
        pis[tid] = (m < M) ? pinv[m] : -1;
    }
    __syncthreads();

    // gather o rows (already half) -> A
    #pragma unroll
    for (int it = 0; it < 4; it++) {
        int flat = it * 256 + tid;        // 1024 uint4 = 64 rows * 16
        int r = flat >> 4, g = flat & 15;
        uint4 u = make_uint4(0, 0, 0, 0);
        if (pis[r] >= 0)
            u = reinterpret_cast<const uint4*>(g_o_h + (size_t)us[r] * 128)[g];
        reinterpret_cast<uint4*>(A)[flat] = u;
    }
    // convert proj_w -> B (layout preserved, col_major fragment)
    #pragma unroll
    for (int it = 0; it < 64; it++) {
        int flat = it * 256 + tid;
        B[flat] = __float2half(W[flat]);
    }
    __syncthreads();

    int w = tid >> 5;
    wmma::fragment<wmma::accumulator, 16, 16, 16, float> fc[4];
    #pragma unroll
    for (int rt = 0; rt < 4; rt++) wmma::fill_fragment(fc[rt], 0.f);
    #pragma unroll
    for (int kk = 0; kk < 8; kk++) {
        wmma::fragment<wmma::matrix_b, 16, 16, 16, __half, wmma::col_major> fb;
        wmma::load_matrix_sync(fb, B + w * 16 * 128 + kk * 16, 128);
        #pragma unroll
        for (int rt = 0; rt < 4; rt++) {
            wmma::fragment<wmma::matrix_a, 16, 16, 16, __half, wmma::row_major> fa;
            wmma::load_matrix_sync(fa, A + rt * 16 * 128 + kk * 16, 128);
            wmma::mma_sync(fc[rt], fa, fb, fc[rt]);
        }
    }
    __syncthreads();   // B dead -> reuse as Cf
    #pragma unroll
    for (int rt = 0; rt < 4; rt++)
        wmma::store_matrix_sync(Cf + rt * 16 * 128 + w * 16, fc[rt], 128,
                                wmma::mem_row_major);
    __syncthreads();

    #pragma unroll
    for (int it = 0; it < 32; it++) {
        int idx = it * 256 + tid;
        int r = idx >> 7, c = idx & 127;
        int pi = pis[r];
        if (pi >= 0)
            atomicAdd(&sums[(size_t)pi * 128 + c], Cf[idx] + bias[c]);
    }
    if (tid < 64 && pis[tid] >= 0) atomicAdd(&g_cnt[pis[tid]], 1.0f);
}

// ---------------------------------------------------------------------------
// Kernel 4: residual + LN2 + FC1 + GELU + FC2 + residual (tensor cores).
// 64 rows/block, 256 threads.
// smem: xf f32[64*128], stat[128], A half[64*128], BC union(32KB), u half[64*512]
// ---------------------------------------------------------------------------
__global__ __launch_bounds__(256) void mlp_tc(
    const float* __restrict__ feat,
    const float* __restrict__ g2, const float* __restrict__ b2,
    const float* __restrict__ fc1_w, const float* __restrict__ fc1_b,
    const float* __restrict__ fc2_w, const float* __restrict__ fc2_b,
    float* __restrict__ out)
{
    extern __shared__ char smraw[];
    float*  xf   = reinterpret_cast<float*>(smraw);            // 32768
    float*  stat = reinterpret_cast<float*>(smraw + 32768);    // 512
    __half* A    = reinterpret_cast<__half*>(smraw + 33280);   // 16384
    __half* B    = reinterpret_cast<__half*>(smraw + 49664);   // 32768 (union C)
    float*  Cf   = reinterpret_cast<float*>(smraw + 49664);
    __half* u    = reinterpret_cast<__half*>(smraw + 82432);   // 65536
    int tid = threadIdx.x;
    int row0 = blockIdx.x * 64;

    // x = feat + sums/max(cnt,1)
    #pragma unroll
    for (int it = 0; it < 32; it++) {
        int idx = it * 256 + tid;
        int r = idx >> 7;
        int row = row0 + r;
        float cv = g_cnt[row];
        xf[idx] = feat[(size_t)row0 * 128 + idx] +
                  out[(size_t)row0 * 128 + idx] / fmaxf(cv, 1.0f);
    }
    __syncthreads();

    // LN2 stats
    {
        int r = tid >> 2, j = tid & 3;
        float s = 0.f, ss = 0.f;
        #pragma unroll
        for (int it = 0; it < 32; it++) {
            float v = xf[r * 128 + j * 32 + it];
            s += v; ss += v * v;
        }
        s  += __shfl_down_sync(0xffffffffu, s, 2, 4);
        ss += __shfl_down_sync(0xffffffffu, ss, 2, 4);
        s  += __shfl_down_sync(0xffffffffu, s, 1, 4);
        ss += __shfl_down_sync(0xffffffffu, ss, 1, 4);
        if (j == 0) {
            float mean = s * 0.0078125f;
            float var  = ss * 0.0078125f - mean * mean;
            stat[r * 2]     = mean;
            stat[r * 2 + 1] = rsqrtf(var + 1e-5f);
        }
    }
    __syncthreads();

    // h2 -> A (half)
    #pragma unroll
    for (int it = 0; it < 32; it++) {
        int idx = it * 256 + tid;
        int r = idx >> 7, c = idx & 127;
        float v = (xf[idx] - stat[r * 2]) * stat[r * 2 + 1] * g2[c] + b2[c];
        A[idx] = __float2half(v);
    }
    __syncthreads();

    int w = tid >> 5;

    // FC1 (128 -> 512) + GELU -> u (half)
    for (int ot = 0; ot < 512; ot += 128) {
        #pragma unroll
        for (int it = 0; it < 64; it++) {
            int flat = it * 256 + tid;
            B[flat] = __float2half(fc1_w[(size_t)ot * 128 + flat]);
        }
        __syncthreads();

        wmma::fragment<wmma::accumulator, 16, 16, 16, float> fc[4];
        #pragma unroll
        for (int rt = 0; rt < 4; rt++) wmma::fill_fragment(fc[rt], 0.f);
        #pragma unroll
        for (int kk = 0; kk < 8; kk++) {
            wmma::fragment<wmma::matrix_b, 16, 16, 16, __half, wmma::col_major> fb;
            wmma::load_matrix_sync(fb, B + w * 16 * 128 + kk * 16, 128);
            #pragma unroll
            for (int rt = 0; rt < 4; rt++) {
                wmma::fragment<wmma::matrix_a, 16, 16, 16, __half, wmma::row_major> fa;
                wmma::load_matrix_sync(fa, A + rt * 16 * 128 + kk * 16, 128);
                wmma::mma_sync(fc[rt], fa, fb, fc[rt]);
            }
        }
        __syncthreads();
        #pragma unroll
        for (int rt = 0; rt < 4; rt++)
            wmma::store_matrix_sync(Cf + rt * 16 * 128 + w * 16, fc[rt], 128,
                                    wmma::mem_row_major);
        __syncthreads();

        #pragma unroll
        for (int it = 0; it < 32; it++) {
            int idx = it * 256 + tid;
            int r = idx >> 7, c = idx & 127;
            float v = Cf[idx] + fc1_b[ot + c];
            float gelu = 0.5f * v * (1.0f + erff(v * 0.70710678118f));
            u[r * 512 + ot + c] = __float2half(gelu);
        }
        __syncthreads();
    }

    // FC2 (512 -> 128), accumulate across 4 k-tiles in registers
    wmma::fragment<wmma::accumulator, 16, 16, 16, float> fc2[4];
    #pragma unroll
    for (int rt = 0; rt < 4; rt++) wmma::fill_fragment(fc2[rt], 0.f);
    for (int kt = 0; kt < 512; kt += 128) {
        #pragma unroll
        for (int it = 0; it < 64; it++) {
            int flat = it * 256 + tid;
            int n = flat >> 7, k = flat & 127;
            B[flat] = __float2half(fc2_w[(size_t)n * 512 + kt + k]);
        }
        __syncthreads();
        #pragma unroll
        for (int kk = 0; kk < 8; kk++) {
            wmma::fragment<wmma::matrix_b, 16, 16, 16, __half, wmma::col_major> fb;
            wmma::load_matrix_sync(fb, B + w * 16 * 128 + kk * 16, 128);
            #pragma unroll
            for (int rt = 0; rt < 4; rt++) {
                wmma::fragment<wmma::matrix_a, 16, 16, 16, __half, wmma::row_major> fa;
                wmma::load_matrix_sync(fa, u + rt * 16 * 512 + kt + kk * 16, 512);
                wmma::mma_sync(fc2[rt], fa, fb, fc2[rt]);
            }
        }
        __syncthreads();
    }
    #pragma unroll
    for (int rt = 0; rt < 4; rt++)
        wmma::store_matrix_sync(Cf + rt * 16 * 128 + w * 16, fc2[rt], 128,
                                wmma::mem_row_major);
    __syncthreads();

    #pragma unroll
    for (int it = 0; it < 32; it++) {
        int idx = it * 256 + tid;
        int c = idx & 127;
        out[(size_t)row0 * 128 + idx] = xf[idx] + Cf[idx] + fc2_b[c];
    }
}

// ---------------------------------------------------------------------------
// Host
// ---------------------------------------------------------------------------
extern "C" void kernel_launch(void* const* d_in, const int* in_sizes, int n_in,
                              void* d_out, int out_size)
{
    const float* feat   = (const float*)d_in[0];
    const float* cosb   = (const float*)d_in[1];
    const float* sinb   = (const float*)d_in[2];
    const float* g1     = (const float*)d_in[3];
    const float* b1     = (const float*)d_in[4];
    const float* qkv_w  = (const float*)d_in[5];
    const float* qkv_b  = (const float*)d_in[6];
    const float* proj_w = (const float*)d_in[7];
    const float* proj_b = (const float*)d_in[8];
    const float* g2     = (const float*)d_in[9];
    const float* b2     = (const float*)d_in[10];
    const float* fc1_w  = (const float*)d_in[11];
    const float* fc1_b  = (const float*)d_in[12];
    const float* fc2_w  = (const float*)d_in[13];
    const float* fc2_b  = (const float*)d_in[14];
    const int*   pinv   = (const int*)d_in[15];
    const int*   pad    = (const int*)d_in[16];
    const int*   unpad  = (const int*)d_in[17];

    int N    = in_sizes[0] / 128;
    int M    = in_sizes[15];
    int Mpad = in_sizes[16];
    int Wn   = Mpad / 48;

    float* out_f = (float*)d_out;

    const int K1_SMEM   = 32768 + 512 + 16384 + 32768;            // 82432
    const int ATTN_SMEM = 3 * 48 * 128 * 4;                        // 73728
    const int K3_SMEM   = 16384 + 32768 + 512;                     // 49664
    const int K4_SMEM   = 32768 + 512 + 16384 + 32768 + 65536;     // 147968

    cudaFuncSetAttribute(ln1_qkv_tc, cudaFuncAttributeMaxDynamicSharedMemorySize, K1_SMEM);
    cudaFuncSetAttribute(attn_kernel, cudaFuncAttributeMaxDynamicSharedMemorySize, ATTN_SMEM);
    cudaFuncSetAttribute(proj_tc,    cudaFuncAttributeMaxDynamicSharedMemorySize, K3_SMEM);
    cudaFuncSetAttribute(mlp_tc,     cudaFuncAttributeMaxDynamicSharedMemorySize, K4_SMEM);

    zero_kernel<<<2048, 256>>>(out_f, N * 128 / 4, N);
    ln1_qkv_tc<<<N / 64, 256, K1_SMEM>>>(feat, g1, b1, qkv_w, qkv_b);
    attn_kernel<<<Wn, 512, ATTN_SMEM>>>(pinv, pad, cosb, sinb);
    proj_tc<<<(M + 63) / 64, 256, K3_SMEM>>>(proj_w, proj_b, unpad, pinv, out_f, M);
    mlp_tc<<<N / 64, 256, K4_SMEM>>>(feat, g2, b2, fc1_w, fc1_b, fc2_w, fc2_b, out_f);
}

// round 6
// speedup vs baseline: 2.1580x; 1.6683x over previous
#include <cuda_runtime.h>
#include <cuda_fp16.h>
#include <mma.h>
#include <math.h>

using namespace nvcuda;

#define NMAX 131072
#define MPAD_MAX 432000

__device__ __half g_qkv_h[(size_t)NMAX * 384];   // ~101 MB
__device__ __half g_o_h[(size_t)MPAD_MAX * 128]; // ~111 MB
__device__ float  g_cnt[NMAX];
// pre-converted fp16 weights (row-major, original layouts)
__device__ __half g_wqkv[384 * 128];
__device__ __half g_wproj[128 * 128];
__device__ __half g_wfc1[512 * 128];
__device__ __half g_wfc2[128 * 512];

// smem strides (padded to break bank-conflict phase alignment)
#define SA 136   // half stride for 128-wide half tiles (272 B)
#define SC 132   // float stride for 128-wide float tiles (528 B)

// ---------------------------------------------------------------------------
// Kernel 0a: zero sums (in d_out) + cnt
// ---------------------------------------------------------------------------
__global__ void zero_kernel(float* __restrict__ sums, int n_sums4, int n_cnt) {
    int i = blockIdx.x * blockDim.x + threadIdx.x;
    int stride = gridDim.x * blockDim.x;
    float4 z = make_float4(0.f, 0.f, 0.f, 0.f);
    float4* s4 = reinterpret_cast<float4*>(sums);
    for (int k = i; k < n_sums4; k += stride) s4[k] = z;
    for (int k = i; k < n_cnt; k += stride) g_cnt[k] = 0.f;
}

// ---------------------------------------------------------------------------
// Kernel 0b: convert all weights fp32 -> fp16 (once per call, ~196K elems)
// ---------------------------------------------------------------------------
__global__ void convw_kernel(const float* __restrict__ qkv_w,
                             const float* __restrict__ proj_w,
                             const float* __restrict__ fc1_w,
                             const float* __restrict__ fc2_w) {
    int i = blockIdx.x * blockDim.x + threadIdx.x;
    int stride = gridDim.x * blockDim.x;
    for (int k = i; k < 384 * 128; k += stride) g_wqkv[k]  = __float2half(qkv_w[k]);
    for (int k = i; k < 128 * 128; k += stride) g_wproj[k] = __float2half(proj_w[k]);
    for (int k = i; k < 512 * 128; k += stride) g_wfc1[k]  = __float2half(fc1_w[k]);
    for (int k = i; k < 128 * 512; k += stride) g_wfc2[k]  = __float2half(fc2_w[k]);
}

// ---------------------------------------------------------------------------
// Kernel 1: LN1 + QKV GEMM (tensor cores). 64 rows/block, 256 threads.
// smem: xf f32[64*SC] (feat buffer + C), stat, A half[64*SA], B half[128*SA]
// ---------------------------------------------------------------------------
__global__ __launch_bounds__(256) void ln1_qkv_tc(
    const float* __restrict__ feat, const float* __restrict__ g1,
    const float* __restrict__ b1, const float* __restrict__ bias)
{
    extern __shared__ char smraw[];
    float*  xf   = reinterpret_cast<float*>(smraw);              // 64*132*4 = 33792
    float*  stat = reinterpret_cast<float*>(smraw + 33792);      // 512
    __half* A    = reinterpret_cast<__half*>(smraw + 34304);     // 64*136*2 = 17408
    __half* B    = reinterpret_cast<__half*>(smraw + 51712);     // 128*136*2 = 34816
    int tid  = threadIdx.x;
    int row0 = blockIdx.x * 64;

    // load 64 rows of feat into padded xf
    #pragma unroll
    for (int it = 0; it < 8; it++) {
        int idx4 = it * 256 + tid;                 // 2048 float4
        int r = idx4 >> 5, c4 = idx4 & 31;
        reinterpret_cast<float4*>(xf)[r * (SC / 4) + c4] =
            reinterpret_cast<const float4*>(feat + (size_t)row0 * 128)[idx4];
    }
    __syncthreads();

    // LN stats: 4 threads per row
    {
        int r = tid >> 2, j = tid & 3;
        float s = 0.f, ss = 0.f;
        #pragma unroll
        for (int it = 0; it < 32; it++) {
            float v = xf[r * SC + j * 32 + it];
            s += v; ss += v * v;
        }
        s  += __shfl_down_sync(0xffffffffu, s, 2, 4);
        ss += __shfl_down_sync(0xffffffffu, ss, 2, 4);
        s  += __shfl_down_sync(0xffffffffu, s, 1, 4);
        ss += __shfl_down_sync(0xffffffffu, ss, 1, 4);
        if (j == 0) {
            float mean = s * 0.0078125f;
            float var  = ss * 0.0078125f - mean * mean;
            stat[r * 2]     = mean;
            stat[r * 2 + 1] = rsqrtf(var + 1e-5f);
        }
    }
    __syncthreads();

    // normalize -> A (half)
    #pragma unroll
    for (int it = 0; it < 32; it++) {
        int idx = it * 256 + tid;
        int r = idx >> 7, c = idx & 127;
        float v = (xf[r * SC + c] - stat[r * 2]) * stat[r * 2 + 1] * g1[c] + b1[c];
        A[r * SA + c] = __float2half(v);
    }
    __syncthreads();

    int w = tid >> 5;
    for (int ot = 0; ot < 384; ot += 128) {
        // B tile from pre-converted half weights (16B vector copies)
        const uint4* src = reinterpret_cast<const uint4*>(g_wqkv + ot * 128);
        #pragma unroll
        for (int it = 0; it < 8; it++) {
            int f = it * 256 + tid;            // 2048 uint4
            int n = f >> 4, k8 = f & 15;
            *reinterpret_cast<uint4*>(B + n * SA + k8 * 8) = src[f];
        }
        __syncthreads();

        wmma::fragment<wmma::accumulator, 16, 16, 16, float> fc[4];
        #pragma unroll
        for (int rt = 0; rt < 4; rt++) wmma::fill_fragment(fc[rt], 0.f);
        #pragma unroll
        for (int kk = 0; kk < 8; kk++) {
            wmma::fragment<wmma::matrix_b, 16, 16, 16, __half, wmma::col_major> fb;
            wmma::load_matrix_sync(fb, B + w * 16 * SA + kk * 16, SA);
            #pragma unroll
            for (int rt = 0; rt < 4; rt++) {
                wmma::fragment<wmma::matrix_a, 16, 16, 16, __half, wmma::row_major> fa;
                wmma::load_matrix_sync(fa, A + rt * 16 * SA + kk * 16, SA);
                wmma::mma_sync(fc[rt], fa, fb, fc[rt]);
            }
        }
        __syncthreads();   // xf free
        #pragma unroll
        for (int rt = 0; rt < 4; rt++)
            wmma::store_matrix_sync(xf + rt * 16 * SC + w * 16, fc[rt], SC,
                                    wmma::mem_row_major);
        __syncthreads();

        #pragma unroll
        for (int it = 0; it < 32; it++) {
            int idx = it * 256 + tid;
            int r = idx >> 7, c = idx & 127;
            g_qkv_h[(size_t)(row0 + r) * 384 + ot + c] =
                __float2half(xf[r * SC + c] + bias[ot + c]);
        }
        __syncthreads();
    }
}

// ---------------------------------------------------------------------------
// Kernel 2: gather + pad + RoPE + windowed attention (unchanged this round).
// ---------------------------------------------------------------------------
__global__ __launch_bounds__(512) void attn_kernel(
    const int* __restrict__ pinv, const int* __restrict__ pad,
    const float* __restrict__ cosb, const float* __restrict__ sinb)
{
    extern __shared__ float sm[];
    float* qs = sm;
    float* ks = sm + 48 * 128;
    float* vs = sm + 2 * 48 * 128;
    int tid = threadIdx.x;
    int w = blockIdx.x;

    if (tid < 384) {
        int r = tid >> 3, seg = tid & 7;
        int pj  = pad[w * 48 + r];
        int src = pinv[pj];
        const uint4* rowp = reinterpret_cast<const uint4*>(g_qkv_h + (size_t)src * 384 + seg * 48);
        #pragma unroll
        for (int blk = 0; blk < 3; blk++) {
            int off = seg * 48 + blk * 16;
            int t = off >> 7, c = off & 127;
            uint4 u0 = rowp[blk * 2 + 0];
            uint4 u1 = rowp[blk * 2 + 1];
            const __half2* hp0 = reinterpret_cast<const __half2*>(&u0);
            const __half2* hp1 = reinterpret_cast<const __half2*>(&u1);
            float vals[16];
            #pragma unroll
            for (int i = 0; i < 4; i++) {
                float2 f = __half22float2(hp0[i]);
                vals[2 * i] = f.x; vals[2 * i + 1] = f.y;
            }
            #pragma unroll
            for (int i = 0; i < 4; i++) {
                float2 f = __half22float2(hp1[i]);
                vals[8 + 2 * i] = f.x; vals[8 + 2 * i + 1] = f.y;
            }
            if (t < 2) {
                #pragma unroll
                for (int d = 0; d < 8; d++) {
                    float cv = cosb[(size_t)pj * 16 + d];
                    float sv = sinb[(size_t)pj * 16 + d];
                    float x1 = vals[d], x2 = vals[d + 8];
                    vals[d]     = x1 * cv - x2 * sv;
                    vals[d + 8] = x2 * cv + x1 * sv;
                }
            }
            float* dst = (t == 0) ? qs : ((t == 1) ? ks : vs);
            float4* d4 = reinterpret_cast<float4*>(dst + r * 128 + c);
            d4[0] = make_float4(vals[0], vals[1], vals[2], vals[3]);
            d4[1] = make_float4(vals[4], vals[5], vals[6], vals[7]);
            d4[2] = make_float4(vals[8], vals[9], vals[10], vals[11]);
            d4[3] = make_float4(vals[12], vals[13], vals[14], vals[15]);
        }
    }
    __syncthreads();

    int h = tid >> 6;
    int r = tid & 63;
    if (r < 48) {
        const float4* qp = reinterpret_cast<const float4*>(qs + r * 128 + h * 16);
        float4 q0 = qp[0], q1 = qp[1], q2 = qp[2], q3 = qp[3];

        float sc[48];
        float mx = -1e30f;
        #pragma unroll
        for (int kk = 0; kk < 48; kk++) {
            const float4* kp = reinterpret_cast<const float4*>(ks + kk * 128 + h * 16);
            float4 k0 = kp[0], k1 = kp[1], k2 = kp[2], k3 = kp[3];
            float a = q0.x * k0.x + q0.y * k0.y + q0.z * k0.z + q0.w * k0.w
                    + q1.x * k1.x + q1.y * k1.y + q1.z * k1.z + q1.w * k1.w
                    + q2.x * k2.x + q2.y * k2.y + q2.z * k2.z + q2.w * k2.w
                    + q3.x * k3.x + q3.y * k3.y + q3.z * k3.z + q3.w * k3.w;
            a *= 0.25f;
            sc[kk] = a;
            mx = fmaxf(mx, a);
        }
        float sum = 0.f;
        #pragma unroll
        for (int kk = 0; kk < 48; kk++) {
            float e = __expf(sc[kk] - mx);
            sc[kk] = e;
            sum += e;
        }
        float inv = 1.f / sum;
        float acc[16];
        #pragma unroll
        for (int d = 0; d < 16; d++) acc[d] = 0.f;
        #pragma unroll
        for (int kk = 0; kk < 48; kk++) {
            float p = sc[kk] * inv;
            const float4* vp = reinterpret_cast<const float4*>(vs + kk * 128 + h * 16);
            float4 v0 = vp[0], v1 = vp[1], v2 = vp[2], v3 = vp[3];
            acc[0] += p * v0.x;  acc[1] += p * v0.y;  acc[2] += p * v0.z;  acc[3] += p * v0.w;
            acc[4] += p * v1.x;  acc[5] += p * v1.y;  acc[6] += p * v1.z;  acc[7] += p * v1.w;
            acc[8] += p * v2.x;  acc[9] += p * v2.y;  acc[10] += p * v2.z; acc[11] += p * v2.w;
            acc[12] += p * v3.x; acc[13] += p * v3.y; acc[14] += p * v3.z; acc[15] += p * v3.w;
        }
        uint4 ou[2];
        __half2* oh = reinterpret_cast<__half2*>(ou);
        #pragma unroll
        for (int i = 0; i < 8; i++)
            oh[i] = __floats2half2_rn(acc[2 * i], acc[2 * i + 1]);
        uint4* op = reinterpret_cast<uint4*>(g_o_h + (size_t)(w * 48 + r) * 128 + h * 16);
        op[0] = ou[0];
        op[1] = ou[1];
    }
}

// ---------------------------------------------------------------------------
// Kernel 3: unpad gather + proj GEMM (TC) + segment scatter-add.
// smem: A half[64*SA], B half[128*SA] (union C f32[64*SC]), idx
// ---------------------------------------------------------------------------
__global__ __launch_bounds__(256) void proj_tc(
    const float* __restrict__ bias,
    const int* __restrict__ unpad, const int* __restrict__ pinv,
    float* __restrict__ sums, int M)
{
    extern __shared__ char smraw[];
    __half* A  = reinterpret_cast<__half*>(smraw);             // 17408
    __half* B  = reinterpret_cast<__half*>(smraw + 17408);     // 34816 (union C)
    float*  Cf = reinterpret_cast<float*>(smraw + 17408);
    int*    us  = reinterpret_cast<int*>(smraw + 52224);       // 64
    int*    pis = us + 64;                                     // 64
    int tid = threadIdx.x;
    int m0 = blockIdx.x * 64;

    if (tid < 64) {
        int m = m0 + tid;
        us[tid]  = (m < M) ? unpad[m] : 0;
        pis[tid] = (m < M) ? pinv[m] : -1;
    }
    __syncthreads();

    // gather o rows (half) -> A padded
    #pragma unroll
    for (int it = 0; it < 4; it++) {
        int f = it * 256 + tid;           // 1024: 64 rows * 16 chunks
        int r = f >> 4, g = f & 15;
        uint4 u = make_uint4(0, 0, 0, 0);
        if (pis[r] >= 0)
            u = reinterpret_cast<const uint4*>(g_o_h + (size_t)us[r] * 128)[g];
        *reinterpret_cast<uint4*>(A + r * SA + g * 8) = u;
    }
    // B from pre-converted proj weights
    {
        const uint4* src = reinterpret_cast<const uint4*>(g_wproj);
        #pragma unroll
        for (int it = 0; it < 8; it++) {
            int f = it * 256 + tid;
            int n = f >> 4, k8 = f & 15;
            *reinterpret_cast<uint4*>(B + n * SA + k8 * 8) = src[f];
        }
    }
    __syncthreads();

    int w = tid >> 5;
    wmma::fragment<wmma::accumulator, 16, 16, 16, float> fc[4];
    #pragma unroll
    for (int rt = 0; rt < 4; rt++) wmma::fill_fragment(fc[rt], 0.f);
    #pragma unroll
    for (int kk = 0; kk < 8; kk++) {
        wmma::fragment<wmma::matrix_b, 16, 16, 16, __half, wmma::col_major> fb;
        wmma::load_matrix_sync(fb, B + w * 16 * SA + kk * 16, SA);
        #pragma unroll
        for (int rt = 0; rt < 4; rt++) {
            wmma::fragment<wmma::matrix_a, 16, 16, 16, __half, wmma::row_major> fa;
            wmma::load_matrix_sync(fa, A + rt * 16 * SA + kk * 16, SA);
            wmma::mma_sync(fc[rt], fa, fb, fc[rt]);
        }
    }
    __syncthreads();
    #pragma unroll
    for (int rt = 0; rt < 4; rt++)
        wmma::store_matrix_sync(Cf + rt * 16 * SC + w * 16, fc[rt], SC,
                                wmma::mem_row_major);
    __syncthreads();

    #pragma unroll
    for (int it = 0; it < 32; it++) {
        int idx = it * 256 + tid;
        int r = idx >> 7, c = idx & 127;
        int pi = pis[r];
        if (pi >= 0)
            atomicAdd(&sums[(size_t)pi * 128 + c], Cf[r * SC + c] + bias[c]);
    }
    if (tid < 64 && pis[tid] >= 0) atomicAdd(&g_cnt[pis[tid]], 1.0f);
}

// ---------------------------------------------------------------------------
// Kernel 4: residual + LN2 + FC1 + GELU + FC2 + residual (TC, interleaved).
// x spilled to `out` between phases; u holds one 64x128 tile only.
// smem: A half[64*SA], B/C union, u half[64*SA], stat  -> 70144 B, 3 blk/SM
// ---------------------------------------------------------------------------
__global__ __launch_bounds__(256) void mlp_tc(
    const float* __restrict__ feat,
    const float* __restrict__ g2, const float* __restrict__ b2,
    const float* __restrict__ fc1_b, const float* __restrict__ fc2_b,
    float* __restrict__ out)
{
    extern __shared__ char smraw[];
    __half* A    = reinterpret_cast<__half*>(smraw);            // 17408
    __half* B    = reinterpret_cast<__half*>(smraw + 17408);    // 34816 (union Cf)
    float*  Cf   = reinterpret_cast<float*>(smraw + 17408);
    __half* u    = reinterpret_cast<__half*>(smraw + 52224);    // 17408
    float*  stat = reinterpret_cast<float*>(smraw + 69632);     // 512
    int tid = threadIdx.x;
    int row0 = blockIdx.x * 64;

    // x = feat + sums/max(cnt,1) -> Cf
    #pragma unroll
    for (int it = 0; it < 32; it++) {
        int idx = it * 256 + tid;
        int r = idx >> 7, c = idx & 127;
        int row = row0 + r;
        float cv = g_cnt[row];
        Cf[r * SC + c] = feat[(size_t)row0 * 128 + idx] +
                         out[(size_t)row0 * 128 + idx] / fmaxf(cv, 1.0f);
    }
    __syncthreads();

    // LN2 stats
    {
        int r = tid >> 2, j = tid & 3;
        float s = 0.f, ss = 0.f;
        #pragma unroll
        for (int it = 0; it < 32; it++) {
            float v = Cf[r * SC + j * 32 + it];
            s += v; ss += v * v;
        }
        s  += __shfl_down_sync(0xffffffffu, s, 2, 4);
        ss += __shfl_down_sync(0xffffffffu, ss, 2, 4);
        s  += __shfl_down_sync(0xffffffffu, s, 1, 4);
        ss += __shfl_down_sync(0xffffffffu, ss, 1, 4);
        if (j == 0) {
            float mean = s * 0.0078125f;
            float var  = ss * 0.0078125f - mean * mean;
            stat[r * 2]     = mean;
            stat[r * 2 + 1] = rsqrtf(var + 1e-5f);
        }
    }
    __syncthreads();

    // h2 -> A (half); spill x to out
    #pragma unroll
    for (int it = 0; it < 32; it++) {
        int idx = it * 256 + tid;
        int r = idx >> 7, c = idx & 127;
        float xv = Cf[r * SC + c];
        A[r * SA + c] = __float2half((xv - stat[r * 2]) * stat[r * 2 + 1] * g2[c] + b2[c]);
        out[(size_t)row0 * 128 + idx] = xv;
    }
    __syncthreads();

    int w = tid >> 5;
    wmma::fragment<wmma::accumulator, 16, 16, 16, float> acc2[4];
    #pragma unroll
    for (int rt = 0; rt < 4; rt++) wmma::fill_fragment(acc2[rt], 0.f);

    for (int kt = 0; kt < 4; kt++) {
        int ot = kt * 128;
        // B = fc1_w tile
        {
            const uint4* src = reinterpret_cast<const uint4*>(g_wfc1 + ot * 128);
            #pragma unroll
            for (int it = 0; it < 8; it++) {
                int f = it * 256 + tid;
                int n = f >> 4, k8 = f & 15;
                *reinterpret_cast<uint4*>(B + n * SA + k8 * 8) = src[f];
            }
        }
        __syncthreads();

        wmma::fragment<wmma::accumulator, 16, 16, 16, float> f1[4];
        #pragma unroll
        for (int rt = 0; rt < 4; rt++) wmma::fill_fragment(f1[rt], 0.f);
        #pragma unroll
        for (int kk = 0; kk < 8; kk++) {
            wmma::fragment<wmma::matrix_b, 16, 16, 16, __half, wmma::col_major> fb;
            wmma::load_matrix_sync(fb, B + w * 16 * SA + kk * 16, SA);
            #pragma unroll
            for (int rt = 0; rt < 4; rt++) {
                wmma::fragment<wmma::matrix_a, 16, 16, 16, __half, wmma::row_major> fa;
                wmma::load_matrix_sync(fa, A + rt * 16 * SA + kk * 16, SA);
                wmma::mma_sync(f1[rt], fa, fb, f1[rt]);
            }
        }
        __syncthreads();        // B dead -> Cf
        #pragma unroll
        for (int rt = 0; rt < 4; rt++)
            wmma::store_matrix_sync(Cf + rt * 16 * SC + w * 16, f1[rt], SC,
                                    wmma::mem_row_major);
        __syncthreads();

        // GELU -> u tile (half)
        #pragma unroll
        for (int it = 0; it < 32; it++) {
            int idx = it * 256 + tid;
            int r = idx >> 7, c = idx & 127;
            float v = Cf[r * SC + c] + fc1_b[ot + c];
            u[r * SA + c] = __float2half(0.5f * v * (1.0f + erff(v * 0.70710678118f)));
        }
        __syncthreads();

        // B = fc2_w k-tile (fc2_w is [128 x 512] row-major)
        {
            #pragma unroll
            for (int it = 0; it < 8; it++) {
                int f = it * 256 + tid;
                int n = f >> 4, k8 = f & 15;
                *reinterpret_cast<uint4*>(B + n * SA + k8 * 8) =
                    reinterpret_cast<const uint4*>(g_wfc2)[n * 64 + kt * 16 + k8];
            }
        }
        __syncthreads();

        #pragma unroll
        for (int kk = 0; kk < 8; kk++) {
            wmma::fragment<wmma::matrix_b, 16, 16, 16, __half, wmma::col_major> fb;
            wmma::load_matrix_sync(fb, B + w * 16 * SA + kk * 16, SA);
            #pragma unroll
            for (int rt = 0; rt < 4; rt++) {
                wmma::fragment<wmma::matrix_a, 16, 16, 16, __half, wmma::row_major> fa;
                wmma::load_matrix_sync(fa, u + rt * 16 * SA + kk * 16, SA);
                wmma::mma_sync(acc2[rt], fa, fb, acc2[rt]);
            }
        }
        __syncthreads();
    }

    #pragma unroll
    for (int rt = 0; rt < 4; rt++)
        wmma::store_matrix_sync(Cf + rt * 16 * SC + w * 16, acc2[rt], SC,
                                wmma::mem_row_major);
    __syncthreads();

    #pragma unroll
    for (int it = 0; it < 32; it++) {
        int idx = it * 256 + tid;
        int r = idx >> 7, c = idx & 127;
        size_t gidx = (size_t)row0 * 128 + idx;
        out[gidx] = out[gidx] + Cf[r * SC + c] + fc2_b[c];
    }
}

// ---------------------------------------------------------------------------
// Host
// ---------------------------------------------------------------------------
extern "C" void kernel_launch(void* const* d_in, const int* in_sizes, int n_in,
                              void* d_out, int out_size)
{
    const float* feat   = (const float*)d_in[0];
    const float* cosb   = (const float*)d_in[1];
    const float* sinb   = (const float*)d_in[2];
    const float* g1     = (const float*)d_in[3];
    const float* b1     = (const float*)d_in[4];
    const float* qkv_w  = (const float*)d_in[5];
    const float* qkv_b  = (const float*)d_in[6];
    const float* proj_w = (const float*)d_in[7];
    const float* proj_b = (const float*)d_in[8];
    const float* g2     = (const float*)d_in[9];
    const float* b2     = (const float*)d_in[10];
    const float* fc1_w  = (const float*)d_in[11];
    const float* fc1_b  = (const float*)d_in[12];
    const float* fc2_w  = (const float*)d_in[13];
    const float* fc2_b  = (const float*)d_in[14];
    const int*   pinv   = (const int*)d_in[15];
    const int*   pad    = (const int*)d_in[16];
    const int*   unpad  = (const int*)d_in[17];

    int N    = in_sizes[0] / 128;
    int M    = in_sizes[15];
    int Mpad = in_sizes[16];
    int Wn   = Mpad / 48;

    float* out_f = (float*)d_out;

    const int K1_SMEM   = 33792 + 512 + 17408 + 34816;   // 86528
    const int ATTN_SMEM = 3 * 48 * 128 * 4;              // 73728
    const int K3_SMEM   = 17408 + 34816 + 512;           // 52736
    const int K4_SMEM   = 17408 + 34816 + 17408 + 512;   // 70144

    cudaFuncSetAttribute(ln1_qkv_tc,  cudaFuncAttributeMaxDynamicSharedMemorySize, K1_SMEM);
    cudaFuncSetAttribute(attn_kernel, cudaFuncAttributeMaxDynamicSharedMemorySize, ATTN_SMEM);
    cudaFuncSetAttribute(proj_tc,     cudaFuncAttributeMaxDynamicSharedMemorySize, K3_SMEM);
    cudaFuncSetAttribute(mlp_tc,      cudaFuncAttributeMaxDynamicSharedMemorySize, K4_SMEM);

    zero_kernel<<<2048, 256>>>(out_f, N * 128 / 4, N);
    convw_kernel<<<768, 256>>>(qkv_w, proj_w, fc1_w, fc2_w);
    ln1_qkv_tc<<<N / 64, 256, K1_SMEM>>>(feat, g1, b1, qkv_b);
    attn_kernel<<<Wn, 512, ATTN_SMEM>>>(pinv, pad, cosb, sinb);
    proj_tc<<<(M + 63) / 64, 256, K3_SMEM>>>(proj_b, unpad, pinv, out_f, M);
    mlp_tc<<<N / 64, 256, K4_SMEM>>>(feat, g2, b2, fc1_b, fc2_b, out_f);
}